// round 3
// baseline (speedup 1.0000x reference)
#include <cuda_runtime.h>
#include <math.h>

// ---------------------------------------------------------------------------
// HoloKVAttention: fused QKV(+LoRA) proj -> RoPE+Hadamard phase -> holographic
// KV compression attention -> O proj(+LoRA).  All fp32.
//
// Shapes: B=2, S=2048, HIDDEN=1024, NUM_HEADS=16, HEAD_DIM=64, K_FACTOR=4,
//         LORA_R=64, ns = S/kf = 512.
// ---------------------------------------------------------------------------

#define HID   1024
#define NH    16
#define HD    64
#define KF    4
#define LR    64
#define BATCH 2
#define SEQ   2048
#define NTOK  (BATCH*SEQ)   // 4096
#define NS    (SEQ/KF)      // 512
#define NBH   (BATCH*NH)    // 32

// ------------------------- device scratch (static) -------------------------
__device__ float g_Q[NTOK*HID];
__device__ float g_K[NTOK*HID];
__device__ float g_V[NTOK*HID];
__device__ float g_XAq[NTOK*LR];
__device__ float g_XAv[NTOK*LR];
__device__ float g_XAo[NTOK*LR];
__device__ float g_Qa[NBH*SEQ*HD];     // rope'd, phase * inv_sqrt_d folded, head-major
__device__ float g_Ks[NBH*SEQ*HD];     // rope'd, phase * 0.5 folded
__device__ float g_Vs[NBH*SEQ*HD];     // phase * 0.5 folded
__device__ float g_fullKT[NBH*HD*NS];  // per (bh): [d][slot]  (transposed for GEMM)
__device__ float g_fullV[NBH*NS*HD];   // per (bh): [slot][d]
__device__ float g_scores[(size_t)NBH*SEQ*NS];  // scores -> softmax weights
__device__ float g_wcurr[NBH*SEQ];
__device__ float g_Ohead[NBH*SEQ*HD];
__device__ float g_Otok[NTOK*HID];
__device__ float2 g_cs_tab[SEQ*32];    // rope cos/sin table

// Hadamard CDMA sign: CDMA[step][dim] = H[step][dim%4]
// negative-bit table packed per (step,col): nibble per step: 0x0,0xA,0xC,0x6
__device__ __forceinline__ float hsign(int step, int col) {
    return ((0x6CA0 >> ((step << 2) | (col & 3))) & 1) ? -1.0f : 1.0f;
}

// ------------------------------ generic SGEMM ------------------------------
// C[M,N] = A[M,K] @ B[K,N]  (+ A2[M,K2] @ B2[K2,N] if A2 != nullptr)
// Optionally batched over blockIdx.z with the given element strides.
// causal: 0 = none
//         1 = scores mode: skip block entirely if n0 > (m0+BM-1)/4   (slot mask)
//         2 = PV mode: limit K loop to ((m0+BM-1)/4)+1 rounded up to BK
template<int BM, int BN, int BK, int TM, int TN>
__global__ __launch_bounds__((BM/TM)*(BN/TN))
void sgemm(const float* __restrict__ A, const float* __restrict__ B,
           float* __restrict__ C,
           int M, int N, int K,
           long long sAb, long long sBb, long long sCb,
           const float* __restrict__ A2, const float* __restrict__ B2, int K2,
           int causal)
{
    constexpr int NT = (BM/TM)*(BN/TN);
    __shared__ float As[BK][BM + 4];
    __shared__ float Bs[BK][BN];

    const int m0 = blockIdx.y * BM;
    const int n0 = blockIdx.x * BN;
    if (causal == 1 && n0 > ((m0 + BM - 1) >> 2)) return;
    int kend = K;
    if (causal == 2) {
        int kl = ((m0 + BM - 1) >> 2) + 1;
        kl = (kl + BK - 1) / BK * BK;
        if (kl < kend) kend = kl;
    }
    const long long batch = blockIdx.z;
    A += batch * sAb; B += batch * sBb; C += batch * sCb;

    const int tid = threadIdx.x;
    const int tx = tid % (BN/TN);
    const int ty = tid / (BN/TN);

    float acc[TM][TN];
    #pragma unroll
    for (int i = 0; i < TM; i++)
        #pragma unroll
        for (int j = 0; j < TN; j++) acc[i][j] = 0.0f;

    float ar[TM], br[TN];

    for (int k0 = 0; k0 < kend; k0 += BK) {
        #pragma unroll
        for (int i = tid; i < BM*BK; i += NT) {
            int r = i / BK, c = i % BK;
            As[c][r] = A[(long long)(m0 + r) * K + (k0 + c)];
        }
        #pragma unroll
        for (int i = tid; i < BK*BN; i += NT) {
            int r = i / BN, c = i % BN;
            Bs[r][c] = B[(long long)(k0 + r) * N + (n0 + c)];
        }
        __syncthreads();
        #pragma unroll
        for (int kk = 0; kk < BK; kk++) {
            #pragma unroll
            for (int i = 0; i < TM; i++) ar[i] = As[kk][ty*TM + i];
            #pragma unroll
            for (int j = 0; j < TN; j++) br[j] = Bs[kk][tx*TN + j];
            #pragma unroll
            for (int i = 0; i < TM; i++)
                #pragma unroll
                for (int j = 0; j < TN; j++)
                    acc[i][j] += ar[i] * br[j];
        }
        __syncthreads();
    }

    if (A2 != nullptr) {
        for (int k0 = 0; k0 < K2; k0 += BK) {
            #pragma unroll
            for (int i = tid; i < BM*BK; i += NT) {
                int r = i / BK, c = i % BK;
                As[c][r] = A2[(long long)(m0 + r) * K2 + (k0 + c)];
            }
            #pragma unroll
            for (int i = tid; i < BK*BN; i += NT) {
                int r = i / BN, c = i % BN;
                Bs[r][c] = B2[(long long)(k0 + r) * N + (n0 + c)];
            }
            __syncthreads();
            #pragma unroll
            for (int kk = 0; kk < BK; kk++) {
                #pragma unroll
                for (int i = 0; i < TM; i++) ar[i] = As[kk][ty*TM + i];
                #pragma unroll
                for (int j = 0; j < TN; j++) br[j] = Bs[kk][tx*TN + j];
                #pragma unroll
                for (int i = 0; i < TM; i++)
                    #pragma unroll
                    for (int j = 0; j < TN; j++)
                        acc[i][j] += ar[i] * br[j];
            }
            __syncthreads();
        }
    }

    #pragma unroll
    for (int i = 0; i < TM; i++) {
        long long row = (long long)(m0 + ty*TM + i) * N + n0 + tx*TN;
        #pragma unroll
        for (int j = 0; j < TN; j++) C[row + j] = acc[i][j];
    }
}

// ----------------------------- rope cos/sin table --------------------------
__global__ void rope_table_kernel() {
    int s = blockIdx.x;        // 0..SEQ-1
    int i = threadIdx.x;       // 0..31
    double invf = exp(-(double)i * (log(10000.0) / 32.0));
    double ang  = (double)s * invf;
    g_cs_tab[s*32 + i] = make_float2((float)cos(ang), (float)sin(ang));
}

// --------------- RoPE + Hadamard phase + layout change (token->head) -------
__global__ void rope_phase_kernel() {
    long long idx = (long long)blockIdx.x * blockDim.x + threadIdx.x;
    if (idx >= (long long)NTOK * HID) return;
    int d = (int)(idx & 63);
    int h = (int)((idx >> 6) & 15);
    int t = (int)(idx >> 10);
    int b = t >> 11;            // SEQ = 2048
    int s = t & (SEQ - 1);
    int step = s & 3;
    float sgn = hsign(step, d);

    long long off  = idx;                         // token-major offset == idx
    long long poff = (d < 32) ? off + 32 : off - 32;
    int i = d & 31;
    float2 cs = g_cs_tab[s*32 + i];

    float qv = g_Q[off], qp = g_Q[poff];
    float kv = g_K[off], kp = g_K[poff];
    float qr = (d < 32) ? (qv*cs.x - qp*cs.y) : (qv*cs.x + qp*cs.y);
    float kr = (d < 32) ? (kv*cs.x - kp*cs.y) : (kv*cs.x + kp*cs.y);

    int bh = b*NH + h;
    long long hoff = (long long)(bh*SEQ + s) * HD + d;
    g_Qa[hoff] = qr * sgn * 0.125f;   // * inv_sqrt_d
    g_Ks[hoff] = kr * sgn * 0.5f;     // * 1/sqrt(kf)
    g_Vs[hoff] = g_V[off] * sgn * 0.5f;
}

// ------------------- full_K (transposed) / full_V per slot -----------------
__global__ void reduce_full_kernel() {
    int idx = blockIdx.x * blockDim.x + threadIdx.x;   // NBH*NS*HD = 1M
    if (idx >= NBH*NS*HD) return;
    int d    = idx & 63;
    int slot = (idx >> 6) & (NS - 1);
    int bh   = idx >> 15;     // 6 + 9
    long long base = (long long)(bh*SEQ + slot*KF) * HD + d;
    float sk = 0.f, sv = 0.f;
    #pragma unroll
    for (int j = 0; j < KF; j++) { sk += g_Ks[base + j*HD]; sv += g_Vs[base + j*HD]; }
    g_fullV[idx] = sv;                                  // [bh][slot][d]
    g_fullKT[((long long)bh*HD + d)*NS + slot] = sk;    // [bh][d][slot]
}

// --------- softmax per query (one warp), with current-slot override --------
__global__ void softmax_kernel() {
    int warp = (blockIdx.x * blockDim.x + threadIdx.x) >> 5;
    int lane = threadIdx.x & 31;
    if (warp >= NBH*SEQ) return;
    int bh = warp / SEQ;
    int q  = warp - bh*SEQ;
    int slot = q >> 2, step = q & 3;

    long long qoff = (long long)warp * HD;   // (bh*SEQ+q)*HD
    float qa0 = g_Qa[qoff + lane];
    float qa1 = g_Qa[qoff + lane + 32];

    // current partial K = cumsum of phase'd K rows within the slot
    long long krow = (long long)(bh*SEQ + slot*KF) * HD;
    float pk0 = 0.f, pk1 = 0.f;
    for (int j = 0; j <= step; j++) {
        pk0 += g_Ks[krow + j*HD + lane];
        pk1 += g_Ks[krow + j*HD + lane + 32];
    }
    float cs = qa0*pk0 + qa1*pk1;
    #pragma unroll
    for (int o = 16; o; o >>= 1) cs += __shfl_xor_sync(0xFFFFFFFFu, cs, o);

    float* row = g_scores + (long long)bh*SEQ*NS + (long long)q*NS;

    float m = cs;
    for (int s = lane; s < slot; s += 32) m = fmaxf(m, row[s]);
    #pragma unroll
    for (int o = 16; o; o >>= 1) m = fmaxf(m, __shfl_xor_sync(0xFFFFFFFFu, m, o));

    float e_cs = expf(cs - m);
    float lsum = 0.f;
    for (int s = lane; s < slot; s += 32) {
        float e = expf(row[s] - m);
        row[s] = e;
        lsum += e;
    }
    #pragma unroll
    for (int o = 16; o; o >>= 1) lsum += __shfl_xor_sync(0xFFFFFFFFu, lsum, o);
    float inv = 1.0f / (lsum + e_cs);

    for (int s = lane; s < NS; s += 32) {
        float w;
        if (s < slot)       w = row[s] * inv;
        else if (s == slot) w = e_cs * inv;
        else                w = 0.0f;
        row[s] = w;
    }
    if (lane == 0) g_wcurr[warp] = e_cs * inv;
}

// --- current-slot V correction + output phase + head-major -> token-major --
__global__ void fixup_kernel() {
    int bhq = blockIdx.x;          // NBH*SEQ
    int d = threadIdx.x;           // 64
    int bh = bhq >> 11;            // /SEQ
    int q  = bhq & (SEQ - 1);
    int slot = q >> 2, step = q & 3;

    float out = g_Ohead[(long long)bhq * HD + d];
    long long vrow = (long long)(bh*SEQ + slot*KF) * HD + d;
    float pv = 0.f;
    for (int j = 0; j <= step; j++) pv += g_Vs[vrow + j*HD];
    float fv = g_fullV[((long long)bh*NS + slot) * HD + d];
    float wc = g_wcurr[bhq];
    float val = (out + wc * (pv - fv)) * hsign(step, d) * 2.0f;  // * var_scale

    int b = bh >> 4, h = bh & 15;
    int t = b*SEQ + q;
    g_Otok[(long long)t*HID + h*HD + d] = val;
}

// --------------------------------- launcher --------------------------------
extern "C" void kernel_launch(void* const* d_in, const int* in_sizes, int n_in,
                              void* d_out, int out_size)
{
    (void)in_sizes; (void)n_in; (void)out_size;
    const float* X  = (const float*)d_in[0];
    const float* Wq = (const float*)d_in[1];
    const float* Wk = (const float*)d_in[2];
    const float* Wv = (const float*)d_in[3];
    const float* Wo = (const float*)d_in[4];
    const float* Aq = (const float*)d_in[5];
    const float* Bq = (const float*)d_in[6];
    const float* Av = (const float*)d_in[7];
    const float* Bv = (const float*)d_in[8];
    const float* Ao = (const float*)d_in[9];
    const float* Bo = (const float*)d_in[10];
    float* Y = (float*)d_out;

    float *pQ, *pK, *pV, *pXAq, *pXAv, *pXAo, *pQa, *pKT, *pFV, *pSc, *pOh, *pOt;
    cudaGetSymbolAddress((void**)&pQ,   g_Q);
    cudaGetSymbolAddress((void**)&pK,   g_K);
    cudaGetSymbolAddress((void**)&pV,   g_V);
    cudaGetSymbolAddress((void**)&pXAq, g_XAq);
    cudaGetSymbolAddress((void**)&pXAv, g_XAv);
    cudaGetSymbolAddress((void**)&pXAo, g_XAo);
    cudaGetSymbolAddress((void**)&pQa,  g_Qa);
    cudaGetSymbolAddress((void**)&pKT,  g_fullKT);
    cudaGetSymbolAddress((void**)&pFV,  g_fullV);
    cudaGetSymbolAddress((void**)&pSc,  g_scores);
    cudaGetSymbolAddress((void**)&pOh,  g_Ohead);
    cudaGetSymbolAddress((void**)&pOt,  g_Otok);

    const int NT_BIG = 256;

    // 1) LoRA stage 1: XAq = X @ Aq, XAv = X @ Av   (M=4096, N=64, K=1024)
    {
        dim3 grid(LR/64, NTOK/128, 1);
        sgemm<128,64,8,8,4><<<grid, NT_BIG>>>(X, Aq, pXAq, NTOK, LR, HID,
                                              0,0,0, nullptr, nullptr, 0, 0);
        sgemm<128,64,8,8,4><<<grid, NT_BIG>>>(X, Av, pXAv, NTOK, LR, HID,
                                              0,0,0, nullptr, nullptr, 0, 0);
    }
    // 2) Projections (M=4096, N=1024, K=1024), Q/V fused with LoRA stage 2
    {
        dim3 grid(HID/128, NTOK/128, 1);
        sgemm<128,128,8,8,8><<<grid, NT_BIG>>>(X, Wq, pQ, NTOK, HID, HID,
                                               0,0,0, pXAq, Bq, LR, 0);
        sgemm<128,128,8,8,8><<<grid, NT_BIG>>>(X, Wk, pK, NTOK, HID, HID,
                                               0,0,0, nullptr, nullptr, 0, 0);
        sgemm<128,128,8,8,8><<<grid, NT_BIG>>>(X, Wv, pV, NTOK, HID, HID,
                                               0,0,0, pXAv, Bv, LR, 0);
    }
    // 3) RoPE + phase folding + layout change
    rope_table_kernel<<<SEQ, 32>>>();
    {
        long long tot = (long long)NTOK * HID;
        rope_phase_kernel<<<(unsigned)((tot + 255) / 256), 256>>>();
    }
    // 4) full_K (transposed) / full_V per slot
    reduce_full_kernel<<<(NBH*NS*HD + 255)/256, 256>>>();

    // 5) scores = Qa @ fullKT  (batched over 32 (b,h), causal tile skip)
    {
        dim3 grid(NS/128, SEQ/128, NBH);
        sgemm<128,128,8,8,8><<<grid, NT_BIG>>>(
            pQa, pKT, pSc, SEQ, NS, HD,
            (long long)SEQ*HD, (long long)HD*NS, (long long)SEQ*NS,
            nullptr, nullptr, 0, /*causal=*/1);
    }
    // 6) softmax with current-slot score override; masked weights -> 0
    softmax_kernel<<<(NBH*SEQ*32)/256, 256>>>();

    // 7) Ohead = W @ fullV  (batched, causal K-limit)
    {
        dim3 grid(HD/64, SEQ/128, NBH);
        sgemm<128,64,8,8,4><<<grid, NT_BIG>>>(
            pSc, pFV, pOh, SEQ, HD, NS,
            (long long)SEQ*NS, (long long)NS*HD, (long long)SEQ*HD,
            nullptr, nullptr, 0, /*causal=*/2);
    }
    // 8) current-slot V correction + output phase, to token-major
    fixup_kernel<<<NBH*SEQ, HD>>>();

    // 9) LoRA stage 1 for O, then Y = O @ Wo + XAo @ Bo
    {
        dim3 grid1(LR/64, NTOK/128, 1);
        sgemm<128,64,8,8,4><<<grid1, NT_BIG>>>(pOt, Ao, pXAo, NTOK, LR, HID,
                                               0,0,0, nullptr, nullptr, 0, 0);
        dim3 grid2(HID/128, NTOK/128, 1);
        sgemm<128,128,8,8,8><<<grid2, NT_BIG>>>(pOt, Wo, Y, NTOK, HID, HID,
                                                0,0,0, pXAo, Bo, LR, 0);
    }
}

// round 4
// speedup vs baseline: 1.0001x; 1.0001x over previous
#include <cuda_runtime.h>
#include <math.h>

// ---------------------------------------------------------------------------
// HoloKVAttention: fused QKV(+LoRA) proj -> RoPE+Hadamard phase -> holographic
// KV compression attention -> O proj(+LoRA).  All fp32.
//
// Shapes: B=2, S=2048, HIDDEN=1024, NUM_HEADS=16, HEAD_DIM=64, K_FACTOR=4,
//         LORA_R=64, ns = S/kf = 512.
// ---------------------------------------------------------------------------

#define HID   1024
#define NH    16
#define HD    64
#define KF    4
#define LR    64
#define BATCH 2
#define SEQ   2048
#define NTOK  (BATCH*SEQ)   // 4096
#define NS    (SEQ/KF)      // 512
#define NBH   (BATCH*NH)    // 32

// ------------------------- device scratch (static) -------------------------
__device__ float g_Q[NTOK*HID];
__device__ float g_K[NTOK*HID];
__device__ float g_V[NTOK*HID];
__device__ float g_XAq[NTOK*LR];
__device__ float g_XAv[NTOK*LR];
__device__ float g_XAo[NTOK*LR];
__device__ float g_Qa[NBH*SEQ*HD];     // rope'd, phase * inv_sqrt_d folded, head-major
__device__ float g_Ks[NBH*SEQ*HD];     // rope'd, phase * 0.5 folded
__device__ float g_Vs[NBH*SEQ*HD];     // phase * 0.5 folded
__device__ float g_fullKT[NBH*HD*NS];  // per (bh): [d][slot]  (transposed for GEMM)
__device__ float g_fullV[NBH*NS*HD];   // per (bh): [slot][d]
__device__ float g_scores[(size_t)NBH*SEQ*NS];  // scores -> softmax weights
__device__ float g_wcurr[NBH*SEQ];
__device__ float g_Ohead[NBH*SEQ*HD];
__device__ float g_Otok[NTOK*HID];
__device__ float2 g_cs_tab[SEQ*32];    // rope cos/sin table

// Hadamard CDMA sign: CDMA[step][dim] = H[step][dim%4]
// negative-bit table packed per (step,col): nibble per step: 0x0,0xA,0xC,0x6
__device__ __forceinline__ float hsign(int step, int col) {
    return ((0x6CA0 >> ((step << 2) | (col & 3))) & 1) ? -1.0f : 1.0f;
}

// ------------------------------ generic SGEMM ------------------------------
// C[M,N] = A[M,K] @ B[K,N]  (+ A2[M,K2] @ B2[K2,N] if A2 != nullptr)
// Optionally batched over blockIdx.z with the given element strides.
// causal: 0 = none
//         1 = scores mode: skip block entirely if n0 > (m0+BM-1)/4   (slot mask)
//         2 = PV mode: limit K loop to ((m0+BM-1)/4)+1 rounded up to BK
template<int BM, int BN, int BK, int TM, int TN>
__global__ __launch_bounds__((BM/TM)*(BN/TN))
void sgemm(const float* __restrict__ A, const float* __restrict__ B,
           float* __restrict__ C,
           int M, int N, int K,
           long long sAb, long long sBb, long long sCb,
           const float* __restrict__ A2, const float* __restrict__ B2, int K2,
           int causal)
{
    constexpr int NT = (BM/TM)*(BN/TN);
    __shared__ float As[BK][BM + 4];
    __shared__ float Bs[BK][BN];

    const int m0 = blockIdx.y * BM;
    const int n0 = blockIdx.x * BN;
    if (causal == 1 && n0 > ((m0 + BM - 1) >> 2)) return;
    int kend = K;
    if (causal == 2) {
        int kl = ((m0 + BM - 1) >> 2) + 1;
        kl = (kl + BK - 1) / BK * BK;
        if (kl < kend) kend = kl;
    }
    const long long batch = blockIdx.z;
    A += batch * sAb; B += batch * sBb; C += batch * sCb;

    const int tid = threadIdx.x;
    const int tx = tid % (BN/TN);
    const int ty = tid / (BN/TN);

    float acc[TM][TN];
    #pragma unroll
    for (int i = 0; i < TM; i++)
        #pragma unroll
        for (int j = 0; j < TN; j++) acc[i][j] = 0.0f;

    float ar[TM], br[TN];

    for (int k0 = 0; k0 < kend; k0 += BK) {
        #pragma unroll
        for (int i = tid; i < BM*BK; i += NT) {
            int r = i / BK, c = i % BK;
            As[c][r] = A[(long long)(m0 + r) * K + (k0 + c)];
        }
        #pragma unroll
        for (int i = tid; i < BK*BN; i += NT) {
            int r = i / BN, c = i % BN;
            Bs[r][c] = B[(long long)(k0 + r) * N + (n0 + c)];
        }
        __syncthreads();
        #pragma unroll
        for (int kk = 0; kk < BK; kk++) {
            #pragma unroll
            for (int i = 0; i < TM; i++) ar[i] = As[kk][ty*TM + i];
            #pragma unroll
            for (int j = 0; j < TN; j++) br[j] = Bs[kk][tx*TN + j];
            #pragma unroll
            for (int i = 0; i < TM; i++)
                #pragma unroll
                for (int j = 0; j < TN; j++)
                    acc[i][j] += ar[i] * br[j];
        }
        __syncthreads();
    }

    if (A2 != nullptr) {
        for (int k0 = 0; k0 < K2; k0 += BK) {
            #pragma unroll
            for (int i = tid; i < BM*BK; i += NT) {
                int r = i / BK, c = i % BK;
                As[c][r] = A2[(long long)(m0 + r) * K2 + (k0 + c)];
            }
            #pragma unroll
            for (int i = tid; i < BK*BN; i += NT) {
                int r = i / BN, c = i % BN;
                Bs[r][c] = B2[(long long)(k0 + r) * N + (n0 + c)];
            }
            __syncthreads();
            #pragma unroll
            for (int kk = 0; kk < BK; kk++) {
                #pragma unroll
                for (int i = 0; i < TM; i++) ar[i] = As[kk][ty*TM + i];
                #pragma unroll
                for (int j = 0; j < TN; j++) br[j] = Bs[kk][tx*TN + j];
                #pragma unroll
                for (int i = 0; i < TM; i++)
                    #pragma unroll
                    for (int j = 0; j < TN; j++)
                        acc[i][j] += ar[i] * br[j];
            }
            __syncthreads();
        }
    }

    #pragma unroll
    for (int i = 0; i < TM; i++) {
        long long row = (long long)(m0 + ty*TM + i) * N + n0 + tx*TN;
        #pragma unroll
        for (int j = 0; j < TN; j++) C[row + j] = acc[i][j];
    }
}

// ----------------------------- rope cos/sin table --------------------------
__global__ void rope_table_kernel() {
    int s = blockIdx.x;        // 0..SEQ-1
    int i = threadIdx.x;       // 0..31
    double invf = exp(-(double)i * (log(10000.0) / 32.0));
    double ang  = (double)s * invf;
    g_cs_tab[s*32 + i] = make_float2((float)cos(ang), (float)sin(ang));
}

// --------------- RoPE + Hadamard phase + layout change (token->head) -------
__global__ void rope_phase_kernel() {
    long long idx = (long long)blockIdx.x * blockDim.x + threadIdx.x;
    if (idx >= (long long)NTOK * HID) return;
    int d = (int)(idx & 63);
    int h = (int)((idx >> 6) & 15);
    int t = (int)(idx >> 10);
    int b = t >> 11;            // SEQ = 2048
    int s = t & (SEQ - 1);
    int step = s & 3;
    float sgn = hsign(step, d);

    long long off  = idx;                         // token-major offset == idx
    long long poff = (d < 32) ? off + 32 : off - 32;
    int i = d & 31;
    float2 cs = g_cs_tab[s*32 + i];

    float qv = g_Q[off], qp = g_Q[poff];
    float kv = g_K[off], kp = g_K[poff];
    float qr = (d < 32) ? (qv*cs.x - qp*cs.y) : (qv*cs.x + qp*cs.y);
    float kr = (d < 32) ? (kv*cs.x - kp*cs.y) : (kv*cs.x + kp*cs.y);

    int bh = b*NH + h;
    long long hoff = (long long)(bh*SEQ + s) * HD + d;
    g_Qa[hoff] = qr * sgn * 0.125f;   // * inv_sqrt_d
    g_Ks[hoff] = kr * sgn * 0.5f;     // * 1/sqrt(kf)
    g_Vs[hoff] = g_V[off] * sgn * 0.5f;
}

// ------------------- full_K (transposed) / full_V per slot -----------------
__global__ void reduce_full_kernel() {
    int idx = blockIdx.x * blockDim.x + threadIdx.x;   // NBH*NS*HD = 1M
    if (idx >= NBH*NS*HD) return;
    int d    = idx & 63;
    int slot = (idx >> 6) & (NS - 1);
    int bh   = idx >> 15;     // 6 + 9
    long long base = (long long)(bh*SEQ + slot*KF) * HD + d;
    float sk = 0.f, sv = 0.f;
    #pragma unroll
    for (int j = 0; j < KF; j++) { sk += g_Ks[base + j*HD]; sv += g_Vs[base + j*HD]; }
    g_fullV[idx] = sv;                                  // [bh][slot][d]
    g_fullKT[((long long)bh*HD + d)*NS + slot] = sk;    // [bh][d][slot]
}

// --------- softmax per query (one warp), with current-slot override --------
__global__ void softmax_kernel() {
    int warp = (blockIdx.x * blockDim.x + threadIdx.x) >> 5;
    int lane = threadIdx.x & 31;
    if (warp >= NBH*SEQ) return;
    int bh = warp / SEQ;
    int q  = warp - bh*SEQ;
    int slot = q >> 2, step = q & 3;

    long long qoff = (long long)warp * HD;   // (bh*SEQ+q)*HD
    float qa0 = g_Qa[qoff + lane];
    float qa1 = g_Qa[qoff + lane + 32];

    // current partial K = cumsum of phase'd K rows within the slot
    long long krow = (long long)(bh*SEQ + slot*KF) * HD;
    float pk0 = 0.f, pk1 = 0.f;
    for (int j = 0; j <= step; j++) {
        pk0 += g_Ks[krow + j*HD + lane];
        pk1 += g_Ks[krow + j*HD + lane + 32];
    }
    float cs = qa0*pk0 + qa1*pk1;
    #pragma unroll
    for (int o = 16; o; o >>= 1) cs += __shfl_xor_sync(0xFFFFFFFFu, cs, o);

    float* row = g_scores + (long long)bh*SEQ*NS + (long long)q*NS;

    float m = cs;
    for (int s = lane; s < slot; s += 32) m = fmaxf(m, row[s]);
    #pragma unroll
    for (int o = 16; o; o >>= 1) m = fmaxf(m, __shfl_xor_sync(0xFFFFFFFFu, m, o));

    float e_cs = expf(cs - m);
    float lsum = 0.f;
    for (int s = lane; s < slot; s += 32) {
        float e = expf(row[s] - m);
        row[s] = e;
        lsum += e;
    }
    #pragma unroll
    for (int o = 16; o; o >>= 1) lsum += __shfl_xor_sync(0xFFFFFFFFu, lsum, o);
    float inv = 1.0f / (lsum + e_cs);

    for (int s = lane; s < NS; s += 32) {
        float w;
        if (s < slot)       w = row[s] * inv;
        else if (s == slot) w = e_cs * inv;
        else                w = 0.0f;
        row[s] = w;
    }
    if (lane == 0) g_wcurr[warp] = e_cs * inv;
}

// --- current-slot V correction + output phase + head-major -> token-major --
__global__ void fixup_kernel() {
    int bhq = blockIdx.x;          // NBH*SEQ
    int d = threadIdx.x;           // 64
    int bh = bhq >> 11;            // /SEQ
    int q  = bhq & (SEQ - 1);
    int slot = q >> 2, step = q & 3;

    float out = g_Ohead[(long long)bhq * HD + d];
    long long vrow = (long long)(bh*SEQ + slot*KF) * HD + d;
    float pv = 0.f;
    for (int j = 0; j <= step; j++) pv += g_Vs[vrow + j*HD];
    float fv = g_fullV[((long long)bh*NS + slot) * HD + d];
    float wc = g_wcurr[bhq];
    float val = (out + wc * (pv - fv)) * hsign(step, d) * 2.0f;  // * var_scale

    int b = bh >> 4, h = bh & 15;
    int t = b*SEQ + q;
    g_Otok[(long long)t*HID + h*HD + d] = val;
}

// --------------------------------- launcher --------------------------------
extern "C" void kernel_launch(void* const* d_in, const int* in_sizes, int n_in,
                              void* d_out, int out_size)
{
    (void)in_sizes; (void)n_in; (void)out_size;
    const float* X  = (const float*)d_in[0];
    const float* Wq = (const float*)d_in[1];
    const float* Wk = (const float*)d_in[2];
    const float* Wv = (const float*)d_in[3];
    const float* Wo = (const float*)d_in[4];
    const float* Aq = (const float*)d_in[5];
    const float* Bq = (const float*)d_in[6];
    const float* Av = (const float*)d_in[7];
    const float* Bv = (const float*)d_in[8];
    const float* Ao = (const float*)d_in[9];
    const float* Bo = (const float*)d_in[10];
    float* Y = (float*)d_out;

    float *pQ, *pK, *pV, *pXAq, *pXAv, *pXAo, *pQa, *pKT, *pFV, *pSc, *pOh, *pOt;
    cudaGetSymbolAddress((void**)&pQ,   g_Q);
    cudaGetSymbolAddress((void**)&pK,   g_K);
    cudaGetSymbolAddress((void**)&pV,   g_V);
    cudaGetSymbolAddress((void**)&pXAq, g_XAq);
    cudaGetSymbolAddress((void**)&pXAv, g_XAv);
    cudaGetSymbolAddress((void**)&pXAo, g_XAo);
    cudaGetSymbolAddress((void**)&pQa,  g_Qa);
    cudaGetSymbolAddress((void**)&pKT,  g_fullKT);
    cudaGetSymbolAddress((void**)&pFV,  g_fullV);
    cudaGetSymbolAddress((void**)&pSc,  g_scores);
    cudaGetSymbolAddress((void**)&pOh,  g_Ohead);
    cudaGetSymbolAddress((void**)&pOt,  g_Otok);

    const int NT_BIG = 256;

    // 1) LoRA stage 1: XAq = X @ Aq, XAv = X @ Av   (M=4096, N=64, K=1024)
    {
        dim3 grid(LR/64, NTOK/128, 1);
        sgemm<128,64,8,8,4><<<grid, NT_BIG>>>(X, Aq, pXAq, NTOK, LR, HID,
                                              0,0,0, nullptr, nullptr, 0, 0);
        sgemm<128,64,8,8,4><<<grid, NT_BIG>>>(X, Av, pXAv, NTOK, LR, HID,
                                              0,0,0, nullptr, nullptr, 0, 0);
    }
    // 2) Projections (M=4096, N=1024, K=1024), Q/V fused with LoRA stage 2
    {
        dim3 grid(HID/128, NTOK/128, 1);
        sgemm<128,128,8,8,8><<<grid, NT_BIG>>>(X, Wq, pQ, NTOK, HID, HID,
                                               0,0,0, pXAq, Bq, LR, 0);
        sgemm<128,128,8,8,8><<<grid, NT_BIG>>>(X, Wk, pK, NTOK, HID, HID,
                                               0,0,0, nullptr, nullptr, 0, 0);
        sgemm<128,128,8,8,8><<<grid, NT_BIG>>>(X, Wv, pV, NTOK, HID, HID,
                                               0,0,0, pXAv, Bv, LR, 0);
    }
    // 3) RoPE + phase folding + layout change
    rope_table_kernel<<<SEQ, 32>>>();
    {
        long long tot = (long long)NTOK * HID;
        rope_phase_kernel<<<(unsigned)((tot + 255) / 256), 256>>>();
    }
    // 4) full_K (transposed) / full_V per slot
    reduce_full_kernel<<<(NBH*NS*HD + 255)/256, 256>>>();

    // 5) scores = Qa @ fullKT  (batched over 32 (b,h), causal tile skip)
    {
        dim3 grid(NS/128, SEQ/128, NBH);
        sgemm<128,128,8,8,8><<<grid, NT_BIG>>>(
            pQa, pKT, pSc, SEQ, NS, HD,
            (long long)SEQ*HD, (long long)HD*NS, (long long)SEQ*NS,
            nullptr, nullptr, 0, /*causal=*/1);
    }
    // 6) softmax with current-slot score override; masked weights -> 0
    softmax_kernel<<<(NBH*SEQ*32)/256, 256>>>();

    // 7) Ohead = W @ fullV  (batched, causal K-limit)
    {
        dim3 grid(HD/64, SEQ/128, NBH);
        sgemm<128,64,8,8,4><<<grid, NT_BIG>>>(
            pSc, pFV, pOh, SEQ, HD, NS,
            (long long)SEQ*NS, (long long)NS*HD, (long long)SEQ*HD,
            nullptr, nullptr, 0, /*causal=*/2);
    }
    // 8) current-slot V correction + output phase, to token-major
    fixup_kernel<<<NBH*SEQ, HD>>>();

    // 9) LoRA stage 1 for O, then Y = O @ Wo + XAo @ Bo
    {
        dim3 grid1(LR/64, NTOK/128, 1);
        sgemm<128,64,8,8,4><<<grid1, NT_BIG>>>(pOt, Ao, pXAo, NTOK, LR, HID,
                                               0,0,0, nullptr, nullptr, 0, 0);
        dim3 grid2(HID/128, NTOK/128, 1);
        sgemm<128,128,8,8,8><<<grid2, NT_BIG>>>(pOt, Wo, Y, NTOK, HID, HID,
                                                0,0,0, pXAo, Bo, LR, 0);
    }
}